// round 2
// baseline (speedup 1.0000x reference)
#include <cuda_runtime.h>
#include <math.h>

#define EMBED   1024
#define KDIM    64
#define HEADS   16
#define BATCH   4
#define SEQ     2048
#define TOKENS  (BATCH * SEQ)      /* 8192 */
#define QKVW    (3 * EMBED)        /* 3072 */

// Scratch (allocation-free rule: __device__ globals)
__device__ float g_qkv[(size_t)TOKENS * QKVW];    // [token][3072]: q | k | v, each [h*64+k]
__device__ float g_heads[(size_t)TOKENS * EMBED]; // [token][h*64+k]

// ---------------------------------------------------------------------------
// SGEMM body: 128x128 C tile, BK=8, 256 threads, 8x8 per-thread microtile.
// Athr: &A[(bm + tid/2)*lda + (tid&1)*4]        (A row-major, lda = K stride)
// Bthr: element (row = tid/32, this thread's col) ; advance by k0*ldb
// Cblk: &C[bm*ldc + bn]
// ---------------------------------------------------------------------------
__device__ __forceinline__ void sgemm_tile(
    const float* __restrict__ Athr,
    const float* __restrict__ Bthr, int ldb,
    float* __restrict__ Cblk, int ldc, int Kd)
{
    const int tid = threadIdx.x;
    const int tx = tid & 15, ty = tid >> 4;
    __shared__ float As[8][128];
    __shared__ float Bs[8][128];
    const int arow = tid >> 1, acol = (tid & 1) * 4;
    const int brow = tid >> 5, bcol = (tid & 31) * 4;

    float acc[8][8];
#pragma unroll
    for (int i = 0; i < 8; i++)
#pragma unroll
        for (int j = 0; j < 8; j++) acc[i][j] = 0.f;

    for (int k0 = 0; k0 < Kd; k0 += 8) {
        float4 av = *(const float4*)(Athr + k0);
        float4 bv = *(const float4*)(Bthr + (size_t)k0 * ldb);
        if (k0) __syncthreads();
        As[acol + 0][arow] = av.x;
        As[acol + 1][arow] = av.y;
        As[acol + 2][arow] = av.z;
        As[acol + 3][arow] = av.w;
        *(float4*)&Bs[brow][bcol] = bv;
        __syncthreads();
#pragma unroll
        for (int kk = 0; kk < 8; ++kk) {
            float a[8], b[8];
            *(float4*)(a)     = *(const float4*)&As[kk][ty * 8];
            *(float4*)(a + 4) = *(const float4*)&As[kk][ty * 8 + 4];
            *(float4*)(b)     = *(const float4*)&Bs[kk][tx * 8];
            *(float4*)(b + 4) = *(const float4*)&Bs[kk][tx * 8 + 4];
#pragma unroll
            for (int i = 0; i < 8; i++)
#pragma unroll
                for (int j = 0; j < 8; j++) acc[i][j] += a[i] * b[j];
        }
    }
#pragma unroll
    for (int i = 0; i < 8; i++) {
        float* crow = Cblk + (size_t)(ty * 8 + i) * ldc + tx * 8;
#pragma unroll
        for (int j = 0; j < 8; j += 4) {
            float4 o = make_float4(acc[i][j], acc[i][j+1], acc[i][j+2], acc[i][j+3]);
            *(float4*)(crow + j) = o;
        }
    }
}

// ---------------------------------------------------------------------------
// Kernel 1: fused QKV projection.  C[8192,3072] = X[8192,1024] @ Wqkv
// Column j: region = j>>10 (0=q,1=k,2=v), head = (j>>6)&15, kcol = j&63.
// Region/head boundaries are 128-aligned, so per-thread pointer setup is
// loop-invariant.
// ---------------------------------------------------------------------------
__global__ void __launch_bounds__(256, 2) qkv_gemm_kernel(
    const float* __restrict__ x,  const float* __restrict__ wq,
    const float* __restrict__ wk, const float* __restrict__ wv)
{
    const int bm = blockIdx.y * 128, bn = blockIdx.x * 128;
    const int tid = threadIdx.x;
    const int arow = tid >> 1, acol = (tid & 1) * 4;
    const int brow = tid >> 5, bcol = (tid & 31) * 4;

    const int j = bn + bcol;
    const int which = j >> 10;
    const float* wsel = (which == 0) ? wq : (which == 1) ? wk : wv;
    const int h = (j >> 6) & (HEADS - 1);
    const int kc = j & (KDIM - 1);
    // element (d = brow, col kc) of head h: wsel[h*1024*64 + d*64 + kc]
    const float* Bthr = wsel + ((size_t)h * EMBED + brow) * KDIM + kc;
    const float* Athr = x + (size_t)(bm + arow) * EMBED + acol;
    sgemm_tile(Athr, Bthr, KDIM, g_qkv + (size_t)bm * QKVW + bn, QKVW, EMBED);
}

// ---------------------------------------------------------------------------
// Kernel 2: flash attention, fp32.  One block: 128 query rows for one (b,h).
// 256 threads, micro layout: rows ty*8+i (ty=tid/16), cols tx*4+j (tx=tid%16).
// ---------------------------------------------------------------------------
#define ATT_BM 128
#define ATT_BN 64
// shared layout (floats):
#define QS_PITCH 128
#define KS_PITCH 68
#define VS_PITCH 68
#define PS_PITCH 129
#define SM_QS    0
#define SM_KS    (SM_QS + 64 * QS_PITCH)              /* 8192  */
#define SM_VS    (SM_KS + 64 * KS_PITCH)              /* +4352 */
#define SM_PS    (SM_VS + 64 * VS_PITCH)              /* +4352 */
#define SM_FLOATS (SM_PS + 64 * PS_PITCH)             /* +8256 = 25152 */
#define ATT_SMEM_BYTES (SM_FLOATS * 4)                /* 100608 B */

extern __shared__ float att_smem[];

__global__ void __launch_bounds__(256, 2) attn_kernel()
{
    float* Qs = att_smem + SM_QS;  // [d][row]
    float* Ks = att_smem + SM_KS;  // [d][key]
    float* Vs = att_smem + SM_VS;  // [key][d]
    float* Ps = att_smem + SM_PS;  // [key][row]

    const int tid = threadIdx.x;
    const int tx = tid & 15, ty = tid >> 4;
    const int bh = blockIdx.y;
    const int b = bh >> 4, h = bh & (HEADS - 1);
    const int q0 = blockIdx.x * ATT_BM;

    const float* qbase = g_qkv + (size_t)b * SEQ * QKVW + h * KDIM;
    const float* kbase = qbase + EMBED;
    const float* vbase = qbase + 2 * EMBED;

    // Load Q tile transposed into Qs[d][r]
    {
        const int r = tid >> 1, d0 = (tid & 1) * 32;
        const float* src = qbase + (size_t)(q0 + r) * QKVW + d0;
#pragma unroll
        for (int u = 0; u < 32; u += 4) {
            float4 v = *(const float4*)(src + u);
            Qs[(d0 + u + 0) * QS_PITCH + r] = v.x;
            Qs[(d0 + u + 1) * QS_PITCH + r] = v.y;
            Qs[(d0 + u + 2) * QS_PITCH + r] = v.z;
            Qs[(d0 + u + 3) * QS_PITCH + r] = v.w;
        }
    }

    float m_i[8], l_i[8], acc[8][4];
#pragma unroll
    for (int i = 0; i < 8; i++) {
        m_i[i] = -1e30f; l_i[i] = 0.f;
#pragma unroll
        for (int j = 0; j < 4; j++) acc[i][j] = 0.f;
    }
    const float scale = 0.125f;  // 1/sqrt(64)

    for (int kt = 0; kt < SEQ; kt += ATT_BN) {
        __syncthreads();   // prior-iter reads of Ks/Vs/Ps done; Qs store ordered (1st iter)
        // Load K (transposed) and V (natural) tiles
        {
            const int c = tid >> 2, d0 = (tid & 3) * 16;
            const float* ksrc = kbase + (size_t)(kt + c) * QKVW + d0;
            const float* vsrc = vbase + (size_t)(kt + c) * QKVW + d0;
#pragma unroll
            for (int u = 0; u < 16; u += 4) {
                float4 k4 = *(const float4*)(ksrc + u);
                Ks[(d0 + u + 0) * KS_PITCH + c] = k4.x;
                Ks[(d0 + u + 1) * KS_PITCH + c] = k4.y;
                Ks[(d0 + u + 2) * KS_PITCH + c] = k4.z;
                Ks[(d0 + u + 3) * KS_PITCH + c] = k4.w;
                *(float4*)&Vs[c * VS_PITCH + d0 + u] = *(const float4*)(vsrc + u);
            }
        }
        __syncthreads();

        // S tile: s[i][j] = sum_d Q[r][d] * K[c][d]
        float s[8][4];
#pragma unroll
        for (int i = 0; i < 8; i++)
#pragma unroll
            for (int j = 0; j < 4; j++) s[i][j] = 0.f;
#pragma unroll 8
        for (int d = 0; d < 64; ++d) {
            float a[8], bb[4];
            *(float4*)(a)     = *(const float4*)&Qs[d * QS_PITCH + ty * 8];
            *(float4*)(a + 4) = *(const float4*)&Qs[d * QS_PITCH + ty * 8 + 4];
            *(float4*)(bb)    = *(const float4*)&Ks[d * KS_PITCH + tx * 4];
#pragma unroll
            for (int i = 0; i < 8; i++)
#pragma unroll
                for (int j = 0; j < 4; j++) s[i][j] += a[i] * bb[j];
        }

        // Online softmax (row stats shared by the 16 tx lanes via shfl, width 16)
#pragma unroll
        for (int i = 0; i < 8; i++) {
            float lm = -1e30f;
#pragma unroll
            for (int j = 0; j < 4; j++) { s[i][j] *= scale; lm = fmaxf(lm, s[i][j]); }
#pragma unroll
            for (int off = 8; off; off >>= 1)
                lm = fmaxf(lm, __shfl_xor_sync(0xffffffffu, lm, off, 16));
            const float mn = fmaxf(m_i[i], lm);
            const float f = __expf(m_i[i] - mn);
            m_i[i] = mn;
            float ls = 0.f;
#pragma unroll
            for (int j = 0; j < 4; j++) {
                float p = __expf(s[i][j] - mn);
                s[i][j] = p; ls += p;
            }
#pragma unroll
            for (int off = 8; off; off >>= 1)
                ls += __shfl_xor_sync(0xffffffffu, ls, off, 16);
            l_i[i] = l_i[i] * f + ls;
#pragma unroll
            for (int j = 0; j < 4; j++) acc[i][j] *= f;
#pragma unroll
            for (int j = 0; j < 4; j++)
                Ps[(tx * 4 + j) * PS_PITCH + ty * 8 + i] = s[i][j];
        }
        __syncthreads();

        // acc += P @ V
#pragma unroll 4
        for (int c = 0; c < ATT_BN; ++c) {
            float a[8];
#pragma unroll
            for (int i = 0; i < 8; i++) a[i] = Ps[c * PS_PITCH + ty * 8 + i];
            const float4 bv = *(const float4*)&Vs[c * VS_PITCH + tx * 4];
            const float bb[4] = {bv.x, bv.y, bv.z, bv.w};
#pragma unroll
            for (int i = 0; i < 8; i++)
#pragma unroll
                for (int j = 0; j < 4; j++) acc[i][j] += a[i] * bb[j];
        }
    }

    // Epilogue: heads[(b*SEQ + q0 + r)][h*64 + c] = acc / l
#pragma unroll
    for (int i = 0; i < 8; i++) {
        const float inv = 1.0f / l_i[i];
        float4 o = make_float4(acc[i][0]*inv, acc[i][1]*inv, acc[i][2]*inv, acc[i][3]*inv);
        *(float4*)&g_heads[(size_t)(b * SEQ + q0 + ty * 8 + i) * EMBED + h * KDIM + tx * 4] = o;
    }
}

// ---------------------------------------------------------------------------
// Kernel 3: output projection.  out[8192,1024] = heads[8192,1024] @ w[1024,1024]
// ---------------------------------------------------------------------------
__global__ void __launch_bounds__(256, 2) out_gemm_kernel(
    const float* __restrict__ w, float* __restrict__ out)
{
    const int bm = blockIdx.y * 128, bn = blockIdx.x * 128;
    const int tid = threadIdx.x;
    const int arow = tid >> 1, acol = (tid & 1) * 4;
    const int brow = tid >> 5, bcol = (tid & 31) * 4;
    const float* Athr = g_heads + (size_t)(bm + arow) * EMBED + acol;
    const float* Bthr = w + (size_t)brow * EMBED + bn + bcol;
    sgemm_tile(Athr, Bthr, EMBED, out + (size_t)bm * EMBED + bn, EMBED, EMBED);
}

// ---------------------------------------------------------------------------
extern "C" void kernel_launch(void* const* d_in, const int* in_sizes, int n_in,
                              void* d_out, int out_size)
{
    const float* x  = (const float*)d_in[0];
    const float* wq = (const float*)d_in[1];
    const float* wk = (const float*)d_in[2];
    const float* wv = (const float*)d_in[3];
    const float* w  = (const float*)d_in[4];
    float* out = (float*)d_out;

    // Idempotent, not a stream op — safe under graph capture.
    cudaFuncSetAttribute(attn_kernel,
                         cudaFuncAttributeMaxDynamicSharedMemorySize,
                         ATT_SMEM_BYTES);

    dim3 g1(QKVW / 128, TOKENS / 128);    // 24 x 64
    qkv_gemm_kernel<<<g1, 256>>>(x, wq, wk, wv);

    dim3 g2(SEQ / ATT_BM, BATCH * HEADS); // 16 x 64
    attn_kernel<<<g2, 256, ATT_SMEM_BYTES>>>();

    dim3 g3(EMBED / 128, TOKENS / 128);   // 8 x 64
    out_gemm_kernel<<<g3, 256>>>(w, out);
}

// round 4
// speedup vs baseline: 1.2975x; 1.2975x over previous
#include <cuda_runtime.h>
#include <cstdint>

#define EMBED   1024
#define KDIM    64
#define HEADS   16
#define BATCH   4
#define SEQ     2048
#define TOKENS  (BATCH * SEQ)      /* 8192 */
#define QKVW    (3 * EMBED)        /* 3072 */
#define BH      (BATCH * HEADS)    /* 64   */

// Scratch (allocation-free rule: __device__ globals)
__device__ float g_qkv[(size_t)TOKENS * QKVW];     // 100 MB: q|k|v per token
__device__ float g_heads[(size_t)TOKENS * EMBED];  // 32 MB
__device__ float g_scores[(size_t)BH * SEQ * SEQ]; // 1 GiB: logits -> probs in place
__device__ float g_wt[(size_t)QKVW * EMBED];       // 12 MB: [j][d] = Wqkv^T
__device__ float g_wt2[(size_t)EMBED * EMBED];     // 4 MB:  [n][k] = w^T

__device__ __forceinline__ float tf32r(float a) {   // round-to-nearest tf32
    uint32_t u;
    asm("cvt.rna.tf32.f32 %0, %1;" : "=r"(u) : "f"(a));
    return __uint_as_float(u);
}

__device__ __forceinline__ void mma8(float* c, const uint32_t* a, uint32_t b0, uint32_t b1) {
    asm volatile(
        "mma.sync.aligned.m16n8k8.row.col.f32.tf32.tf32.f32 "
        "{%0,%1,%2,%3}, {%4,%5,%6,%7}, {%8,%9}, {%0,%1,%2,%3};"
        : "+f"(c[0]), "+f"(c[1]), "+f"(c[2]), "+f"(c[3])
        : "r"(a[0]), "r"(a[1]), "r"(a[2]), "r"(a[3]), "r"(b0), "r"(b1));
}

// ---------------------------------------------------------------------------
// Prep: g_wt[j][d] = per-head Wq|Wk|Wv transposed;  g_wt2[n][k] = w^T.
// ---------------------------------------------------------------------------
__global__ void __launch_bounds__(256) prep_kernel(
    const float* __restrict__ wq, const float* __restrict__ wk,
    const float* __restrict__ wv, const float* __restrict__ w)
{
    const int gid = blockIdx.x * 256 + threadIdx.x;
    if (gid < QKVW * 256) {
        const int j = gid >> 8, d0 = (gid & 255) * 4;
        const int which = j >> 10;
        const float* wsel = (which == 0) ? wq : (which == 1) ? wk : wv;
        const float* src = wsel + (size_t)((j >> 6) & (HEADS - 1)) * (EMBED * KDIM)
                                + (j & (KDIM - 1));
        float4 o;
        o.x = src[(size_t)(d0 + 0) * KDIM];
        o.y = src[(size_t)(d0 + 1) * KDIM];
        o.z = src[(size_t)(d0 + 2) * KDIM];
        o.w = src[(size_t)(d0 + 3) * KDIM];
        *(float4*)&g_wt[(size_t)j * EMBED + d0] = o;
    } else {
        const int g2 = gid - QKVW * 256;
        const int j = g2 >> 8, k0 = (g2 & 255) * 4;
        float4 o;
        o.x = w[(size_t)(k0 + 0) * EMBED + j];
        o.y = w[(size_t)(k0 + 1) * EMBED + j];
        o.z = w[(size_t)(k0 + 2) * EMBED + j];
        o.w = w[(size_t)(k0 + 3) * EMBED + j];
        *(float4*)&g_wt2[(size_t)j * EMBED + k0] = o;
    }
}

// ---------------------------------------------------------------------------
// Unified warp-mma tf32 GEMM:  C[128, BN] = A[128, K] @ B^T   (B stored [n][k])
// SPLIT=3: 3xTF32 hi/lo error-compensated; SPLIT=1: plain tf32.
// 256 threads = 8 warps, warp tile 32 x (BN/2), m16n8k8 fragments.
// ---------------------------------------------------------------------------
#define MODE_QKV   0
#define MODE_QKT   1
#define MODE_PV    2
#define MODE_OPROJ 3

#define PA 36              /* smem pitch (floats): conflict-free fragment loads */

template <int MODE, int BN, int SPLIT, int KD>
__global__ void __launch_bounds__(256, 2) gemm_kernel(
    const float* __restrict__ x, float* __restrict__ outp)
{
    extern __shared__ float sf[];
    constexpr int NA   = (SPLIT == 3) ? 2 : 1;
    constexpr int NCH  = KD / 32;
    constexpr int NT   = BN / 16;          /* n-tiles per warp (WN = BN/2)   */
    constexpr int AF   = 128 * PA;         /* floats per A plane             */
    constexpr int BF   = BN * PA;
    constexpr int PEPI = BN + 4;

    float* aHi = sf;
    float* aLo = sf + AF;                  /* valid only if SPLIT==3 */
    float* bHi = sf + AF * NA;
    float* bLo = bHi + BF;

    const int tid  = threadIdx.x;
    const int wid  = tid >> 5;
    const int lane = tid & 31;
    const int g    = lane >> 2;            /* groupID       */
    const int t    = lane & 3;             /* thread in grp */
    const int wm   = (wid & 3) * 32;
    const int wn   = (wid >> 2) * (BN / 2);
    const int bm   = blockIdx.y * 128;

    // ---- mode-dependent operand plumbing (all loads k-contiguous) ----
    const float* Abase; int lda;
    const float* Bbase = nullptr; int ldb = 0;
    const float* Vbase = nullptr;          /* PV: V needs on-the-fly transpose */
    float* Cbase; int ldc;

    if constexpr (MODE == MODE_QKV) {
        Abase = x + (size_t)bm * EMBED;                      lda = EMBED;
        Bbase = g_wt + (size_t)blockIdx.x * 128 * EMBED;     ldb = EMBED;
        Cbase = g_qkv + (size_t)bm * QKVW + blockIdx.x * 128; ldc = QKVW;
    } else if constexpr (MODE == MODE_QKT) {
        const int bh = blockIdx.z;
        const float* base = g_qkv + (size_t)(bh >> 4) * SEQ * QKVW + (bh & 15) * KDIM;
        Abase = base + (size_t)bm * QKVW;                    lda = QKVW;
        Bbase = base + EMBED + (size_t)blockIdx.x * 128 * QKVW; ldb = QKVW;
        Cbase = g_scores + (size_t)bh * SEQ * SEQ + (size_t)bm * SEQ + blockIdx.x * 128;
        ldc = SEQ;
    } else if constexpr (MODE == MODE_PV) {
        const int bh = blockIdx.z;
        Abase = g_scores + (size_t)bh * SEQ * SEQ + (size_t)bm * SEQ;  lda = SEQ;
        Vbase = g_qkv + (size_t)(bh >> 4) * SEQ * QKVW + 2 * EMBED + (bh & 15) * KDIM;
        Cbase = g_heads + ((size_t)(bh >> 4) * SEQ + bm) * EMBED + (bh & 15) * KDIM;
        ldc = EMBED;
    } else { /* OPROJ */
        Abase = g_heads + (size_t)bm * EMBED;                lda = EMBED;
        Bbase = g_wt2 + (size_t)blockIdx.x * 128 * EMBED;    ldb = EMBED;
        Cbase = outp + (size_t)bm * EMBED + blockIdx.x * 128; ldc = EMBED;
    }

    float acc[2][NT][4];
#pragma unroll
    for (int mt = 0; mt < 2; mt++)
#pragma unroll
        for (int nt = 0; nt < NT; nt++)
#pragma unroll
            for (int i = 0; i < 4; i++) acc[mt][nt][i] = 0.f;

    for (int ci = 0; ci < NCH; ++ci) {
        const int k0 = ci * 32;
        if (ci) __syncthreads();   /* prior mma reads done before overwrite */

        // ---- fill A tile [128 x 32] (tf32 split into smem) ----
        {
            const int r = tid >> 1, c0 = (tid & 1) * 16;
            const float* p = Abase + (size_t)r * lda + k0 + c0;
#pragma unroll
            for (int u = 0; u < 16; u += 4) {
                float4 v = *(const float4*)(p + u);
                float* dh = aHi + r * PA + c0 + u;
                if constexpr (SPLIT == 3) {
                    float4 h, l;
                    h.x = tf32r(v.x); l.x = tf32r(v.x - h.x);
                    h.y = tf32r(v.y); l.y = tf32r(v.y - h.y);
                    h.z = tf32r(v.z); l.z = tf32r(v.z - h.z);
                    h.w = tf32r(v.w); l.w = tf32r(v.w - h.w);
                    *(float4*)dh = h;
                    *(float4*)(aLo + r * PA + c0 + u) = l;
                } else {
                    float4 h;
                    h.x = tf32r(v.x); h.y = tf32r(v.y);
                    h.z = tf32r(v.z); h.w = tf32r(v.w);
                    *(float4*)dh = h;
                }
            }
        }
        // ---- fill B tile [BN x 32] ----
        if constexpr (MODE == MODE_PV) {
            // V rows are n-contiguous: load float4 along n, scatter along k.
#pragma unroll
            for (int it = 0; it < 2; ++it) {
                const int task = tid + it * 256;
                const int tok = task >> 4, q = (task & 15) * 4;
                float4 v = *(const float4*)(Vbase + (size_t)(k0 + tok) * QKVW + q);
                bHi[(q + 0) * PA + tok] = tf32r(v.x);
                bHi[(q + 1) * PA + tok] = tf32r(v.y);
                bHi[(q + 2) * PA + tok] = tf32r(v.z);
                bHi[(q + 3) * PA + tok] = tf32r(v.w);
            }
        } else {
            const int r = tid >> 1, c0 = (tid & 1) * 16;
            const float* p = Bbase + (size_t)r * ldb + k0 + c0;
#pragma unroll
            for (int u = 0; u < 16; u += 4) {
                float4 v = *(const float4*)(p + u);
                if constexpr (SPLIT == 3) {
                    float4 h, l;
                    h.x = tf32r(v.x); l.x = tf32r(v.x - h.x);
                    h.y = tf32r(v.y); l.y = tf32r(v.y - h.y);
                    h.z = tf32r(v.z); l.z = tf32r(v.z - h.z);
                    h.w = tf32r(v.w); l.w = tf32r(v.w - h.w);
                    *(float4*)(bHi + r * PA + c0 + u) = h;
                    *(float4*)(bLo + r * PA + c0 + u) = l;
                } else {
                    float4 h;
                    h.x = tf32r(v.x); h.y = tf32r(v.y);
                    h.z = tf32r(v.z); h.w = tf32r(v.w);
                    *(float4*)(bHi + r * PA + c0 + u) = h;
                }
            }
        }
        __syncthreads();

        // ---- mma over 4 k-steps of 8 ----
#pragma unroll
        for (int ks = 0; ks < 4; ++ks) {
            const int kb = ks * 8;
            uint32_t aH[2][4], aL[2][4];
#pragma unroll
            for (int mt = 0; mt < 2; ++mt) {
                const float* ap = aHi + (wm + mt * 16 + g) * PA + kb + t;
                aH[mt][0] = __float_as_uint(ap[0]);
                aH[mt][1] = __float_as_uint(ap[8 * PA]);
                aH[mt][2] = __float_as_uint(ap[4]);
                aH[mt][3] = __float_as_uint(ap[8 * PA + 4]);
                if constexpr (SPLIT == 3) {
                    const float* al = aLo + (wm + mt * 16 + g) * PA + kb + t;
                    aL[mt][0] = __float_as_uint(al[0]);
                    aL[mt][1] = __float_as_uint(al[8 * PA]);
                    aL[mt][2] = __float_as_uint(al[4]);
                    aL[mt][3] = __float_as_uint(al[8 * PA + 4]);
                }
            }
#pragma unroll
            for (int nt = 0; nt < NT; ++nt) {
                const float* bp = bHi + (wn + nt * 8 + g) * PA + kb + t;
                const uint32_t bH0 = __float_as_uint(bp[0]);
                const uint32_t bH1 = __float_as_uint(bp[4]);
#pragma unroll
                for (int mt = 0; mt < 2; ++mt) mma8(acc[mt][nt], aH[mt], bH0, bH1);
                if constexpr (SPLIT == 3) {
                    const float* bl = bLo + (wn + nt * 8 + g) * PA + kb + t;
                    const uint32_t bL0 = __float_as_uint(bl[0]);
                    const uint32_t bL1 = __float_as_uint(bl[4]);
#pragma unroll
                    for (int mt = 0; mt < 2; ++mt) {
                        mma8(acc[mt][nt], aH[mt], bL0, bL1);
                        mma8(acc[mt][nt], aL[mt], bH0, bH1);
                    }
                }
            }
        }
    }

    // ---- epilogue: stage C through smem for coalesced float4 stores ----
    __syncthreads();
#pragma unroll
    for (int mt = 0; mt < 2; ++mt)
#pragma unroll
        for (int nt = 0; nt < NT; ++nt) {
            const int row = wm + mt * 16 + g;
            const int col = wn + nt * 8 + t * 2;
            *(float2*)&sf[row * PEPI + col]       = make_float2(acc[mt][nt][0], acc[mt][nt][1]);
            *(float2*)&sf[(row + 8) * PEPI + col] = make_float2(acc[mt][nt][2], acc[mt][nt][3]);
        }
    __syncthreads();
#pragma unroll
    for (int i = tid; i < 128 * (BN / 4); i += 256) {
        const int row = i / (BN / 4), c4 = (i % (BN / 4)) * 4;
        *(float4*)(Cbase + (size_t)row * ldc + c4) = *(const float4*)&sf[row * PEPI + c4];
    }
}

// ---------------------------------------------------------------------------
// Row softmax over g_scores (in place); folds in scale 1/sqrt(64).
// ---------------------------------------------------------------------------
__global__ void __launch_bounds__(256) softmax_kernel()
{
    __shared__ float red[8];
    float* row = g_scores + ((size_t)blockIdx.y * SEQ + blockIdx.x) * SEQ;
    const int tid = threadIdx.x, wid = tid >> 5, lane = tid & 31;

    float v[8];
    *(float4*)(v)     = *(const float4*)(row + tid * 8);
    *(float4*)(v + 4) = *(const float4*)(row + tid * 8 + 4);

    float mx = v[0];
#pragma unroll
    for (int i = 1; i < 8; i++) mx = fmaxf(mx, v[i]);
#pragma unroll
    for (int o = 16; o; o >>= 1) mx = fmaxf(mx, __shfl_xor_sync(~0u, mx, o));
    if (lane == 0) red[wid] = mx;
    __syncthreads();
    mx = red[0];
#pragma unroll
    for (int i = 1; i < 8; i++) mx = fmaxf(mx, red[i]);

    const float S = 0.125f;
    const float base = mx * S;
    float sum = 0.f;
#pragma unroll
    for (int i = 0; i < 8; i++) { v[i] = __expf(v[i] * S - base); sum += v[i]; }
#pragma unroll
    for (int o = 16; o; o >>= 1) sum += __shfl_xor_sync(~0u, sum, o);
    __syncthreads();
    if (lane == 0) red[wid] = sum;
    __syncthreads();
    sum = red[0];
#pragma unroll
    for (int i = 1; i < 8; i++) sum += red[i];
    const float inv = 1.0f / sum;
#pragma unroll
    for (int i = 0; i < 8; i++) v[i] *= inv;
    *(float4*)(row + tid * 8)     = *(float4*)(v);
    *(float4*)(row + tid * 8 + 4) = *(float4*)(v + 4);
}

// ---------------------------------------------------------------------------
#define SMF(stage, epi) (((stage) > (epi) ? (stage) : (epi)) * 4)
#define SM_QKV SMF((128 * PA) * 2 + (128 * PA) * 2, 128 * 132)   /* 73728 */
#define SM_QKT SM_QKV                                            /* 73728 */
#define SM_PV  SMF((128 * PA) + (64 * PA), 128 * 68)             /* 34816 */
#define SM_OP  SMF((128 * PA) + (128 * PA), 128 * 132)           /* 67584 */

extern "C" void kernel_launch(void* const* d_in, const int* in_sizes, int n_in,
                              void* d_out, int out_size)
{
    const float* x  = (const float*)d_in[0];
    const float* wq = (const float*)d_in[1];
    const float* wk = (const float*)d_in[2];
    const float* wv = (const float*)d_in[3];
    const float* w  = (const float*)d_in[4];
    float* out = (float*)d_out;

    cudaFuncSetAttribute(gemm_kernel<MODE_QKV,   128, 3, 1024>,
                         cudaFuncAttributeMaxDynamicSharedMemorySize, SM_QKV);
    cudaFuncSetAttribute(gemm_kernel<MODE_QKT,   128, 3,   64>,
                         cudaFuncAttributeMaxDynamicSharedMemorySize, SM_QKT);
    cudaFuncSetAttribute(gemm_kernel<MODE_PV,     64, 1, 2048>,
                         cudaFuncAttributeMaxDynamicSharedMemorySize, SM_PV);
    cudaFuncSetAttribute(gemm_kernel<MODE_OPROJ, 128, 1, 1024>,
                         cudaFuncAttributeMaxDynamicSharedMemorySize, SM_OP);

    // 0. transpose weights once (coalesced mainloop loads)
    prep_kernel<<<(QKVW * 256 + EMBED * 256) / 256, 256>>>(wq, wk, wv, w);

    // 1. QKV projection (3xTF32): g_qkv = x @ [wq|wk|wv]
    gemm_kernel<MODE_QKV, 128, 3, 1024>
        <<<dim3(QKVW / 128, TOKENS / 128), 256, SM_QKV>>>(x, out);

    // 2. logits (3xTF32): g_scores[bh] = Q @ K^T
    gemm_kernel<MODE_QKT, 128, 3, 64>
        <<<dim3(SEQ / 128, SEQ / 128, BH), 256, SM_QKT>>>(x, out);

    // 3. softmax in place (applies 1/8 scale)
    softmax_kernel<<<dim3(SEQ, BH), 256>>>();

    // 4. context (tf32): g_heads[bh] = P @ V
    gemm_kernel<MODE_PV, 64, 1, 2048>
        <<<dim3(1, SEQ / 128, BH), 256, SM_PV>>>(x, out);

    // 5. output projection (tf32): out = heads @ w
    gemm_kernel<MODE_OPROJ, 128, 1, 1024>
        <<<dim3(EMBED / 128, TOKENS / 128), 256, SM_OP>>>(x, out);
}

// round 6
// speedup vs baseline: 1.6883x; 1.3011x over previous
#include <cuda_runtime.h>
#include <cstdint>

#define EMBED   1024
#define KDIM    64
#define HEADS   16
#define BATCH   4
#define SEQ     2048
#define TOKENS  (BATCH * SEQ)      /* 8192 */
#define QKVW    (3 * EMBED)        /* 3072 */
#define BH      (BATCH * HEADS)    /* 64   */

// Scratch (allocation-free rule: __device__ globals)
__device__ float g_qkv[(size_t)TOKENS * QKVW];     // 100 MB: q|k|v per token
__device__ float g_heads[(size_t)TOKENS * EMBED];  // 32 MB
__device__ float g_wt[(size_t)QKVW * EMBED];       // 12 MB: [j][d] = Wqkv^T
__device__ float g_wt2[(size_t)EMBED * EMBED];     // 4 MB:  [n][k] = w^T

__device__ __forceinline__ float tf32r(float a) {   // round-to-nearest tf32
    uint32_t u;
    asm("cvt.rna.tf32.f32 %0, %1;" : "=r"(u) : "f"(a));
    return __uint_as_float(u);
}

__device__ __forceinline__ void mma8(float* c, const uint32_t* a, uint32_t b0, uint32_t b1) {
    asm volatile(
        "mma.sync.aligned.m16n8k8.row.col.f32.tf32.tf32.f32 "
        "{%0,%1,%2,%3}, {%4,%5,%6,%7}, {%8,%9}, {%0,%1,%2,%3};"
        : "+f"(c[0]), "+f"(c[1]), "+f"(c[2]), "+f"(c[3])
        : "r"(a[0]), "r"(a[1]), "r"(a[2]), "r"(a[3]), "r"(b0), "r"(b1));
}

// ---------------------------------------------------------------------------
// Prep: g_wt[j][d] = per-head Wq|Wk|Wv transposed;  g_wt2[n][k] = w^T.
// ---------------------------------------------------------------------------
__global__ void __launch_bounds__(256) prep_kernel(
    const float* __restrict__ wq, const float* __restrict__ wk,
    const float* __restrict__ wv, const float* __restrict__ w)
{
    const int gid = blockIdx.x * 256 + threadIdx.x;
    if (gid < QKVW * 256) {
        const int j = gid >> 8, d0 = (gid & 255) * 4;
        const int which = j >> 10;
        const float* wsel = (which == 0) ? wq : (which == 1) ? wk : wv;
        const float* src = wsel + (size_t)((j >> 6) & (HEADS - 1)) * (EMBED * KDIM)
                                + (j & (KDIM - 1));
        float4 o;
        o.x = src[(size_t)(d0 + 0) * KDIM];
        o.y = src[(size_t)(d0 + 1) * KDIM];
        o.z = src[(size_t)(d0 + 2) * KDIM];
        o.w = src[(size_t)(d0 + 3) * KDIM];
        *(float4*)&g_wt[(size_t)j * EMBED + d0] = o;
    } else {
        const int g2 = gid - QKVW * 256;
        const int j = g2 >> 8, k0 = (g2 & 255) * 4;
        float4 o;
        o.x = w[(size_t)(k0 + 0) * EMBED + j];
        o.y = w[(size_t)(k0 + 1) * EMBED + j];
        o.z = w[(size_t)(k0 + 2) * EMBED + j];
        o.w = w[(size_t)(k0 + 3) * EMBED + j];
        *(float4*)&g_wt2[(size_t)j * EMBED + k0] = o;
    }
}

// ---------------------------------------------------------------------------
// Warp-mma tf32 GEMM (validated R3):  C[128, BN] = A[128, K] @ B^T
// SPLIT=3: 3xTF32 hi/lo compensated; SPLIT=1: plain tf32.
// ---------------------------------------------------------------------------
#define MODE_QKV   0
#define MODE_OPROJ 3

#define PA 36              /* smem pitch (floats): conflict-free fragment loads */

template <int MODE, int BN, int SPLIT, int KD>
__global__ void __launch_bounds__(256, 2) gemm_kernel(
    const float* __restrict__ x, float* __restrict__ outp, int bx0)
{
    extern __shared__ float sf[];
    constexpr int NA   = (SPLIT == 3) ? 2 : 1;
    constexpr int NCH  = KD / 32;
    constexpr int NT   = BN / 16;
    constexpr int AF   = 128 * PA;
    constexpr int BF   = BN * PA;
    constexpr int PEPI = BN + 4;

    float* aHi = sf;
    float* aLo = sf + AF;
    float* bHi = sf + AF * NA;
    float* bLo = bHi + BF;

    const int tid  = threadIdx.x;
    const int wid  = tid >> 5;
    const int lane = tid & 31;
    const int g    = lane >> 2;
    const int t    = lane & 3;
    const int wm   = (wid & 3) * 32;
    const int wn   = (wid >> 2) * (BN / 2);
    const int bm   = blockIdx.y * 128;

    const float* Abase; int lda;
    const float* Bbase; int ldb;
    float* Cbase; int ldc;

    if constexpr (MODE == MODE_QKV) {
        const int j0 = (blockIdx.x + bx0) * 128;
        Abase = x + (size_t)bm * EMBED;                       lda = EMBED;
        Bbase = g_wt + (size_t)j0 * EMBED;                    ldb = EMBED;
        Cbase = g_qkv + (size_t)bm * QKVW + j0;               ldc = QKVW;
    } else { /* OPROJ */
        Abase = g_heads + (size_t)bm * EMBED;                 lda = EMBED;
        Bbase = g_wt2 + (size_t)blockIdx.x * 128 * EMBED;     ldb = EMBED;
        Cbase = outp + (size_t)bm * EMBED + blockIdx.x * 128; ldc = EMBED;
    }

    float acc[2][NT][4];
#pragma unroll
    for (int mt = 0; mt < 2; mt++)
#pragma unroll
        for (int nt = 0; nt < NT; nt++)
#pragma unroll
            for (int i = 0; i < 4; i++) acc[mt][nt][i] = 0.f;

    for (int ci = 0; ci < NCH; ++ci) {
        const int k0 = ci * 32;
        if (ci) __syncthreads();

        {
            const int r = tid >> 1, c0 = (tid & 1) * 16;
            const float* p = Abase + (size_t)r * lda + k0 + c0;
#pragma unroll
            for (int u = 0; u < 16; u += 4) {
                float4 v = *(const float4*)(p + u);
                if constexpr (SPLIT == 3) {
                    float4 h, l;
                    h.x = tf32r(v.x); l.x = tf32r(v.x - h.x);
                    h.y = tf32r(v.y); l.y = tf32r(v.y - h.y);
                    h.z = tf32r(v.z); l.z = tf32r(v.z - h.z);
                    h.w = tf32r(v.w); l.w = tf32r(v.w - h.w);
                    *(float4*)(aHi + r * PA + c0 + u) = h;
                    *(float4*)(aLo + r * PA + c0 + u) = l;
                } else {
                    float4 h;
                    h.x = tf32r(v.x); h.y = tf32r(v.y);
                    h.z = tf32r(v.z); h.w = tf32r(v.w);
                    *(float4*)(aHi + r * PA + c0 + u) = h;
                }
            }
        }
        {
            const int r = tid >> 1, c0 = (tid & 1) * 16;
            const float* p = Bbase + (size_t)r * ldb + k0 + c0;
#pragma unroll
            for (int u = 0; u < 16; u += 4) {
                float4 v = *(const float4*)(p + u);
                if constexpr (SPLIT == 3) {
                    float4 h, l;
                    h.x = tf32r(v.x); l.x = tf32r(v.x - h.x);
                    h.y = tf32r(v.y); l.y = tf32r(v.y - h.y);
                    h.z = tf32r(v.z); l.z = tf32r(v.z - h.z);
                    h.w = tf32r(v.w); l.w = tf32r(v.w - h.w);
                    *(float4*)(bHi + r * PA + c0 + u) = h;
                    *(float4*)(bLo + r * PA + c0 + u) = l;
                } else {
                    float4 h;
                    h.x = tf32r(v.x); h.y = tf32r(v.y);
                    h.z = tf32r(v.z); h.w = tf32r(v.w);
                    *(float4*)(bHi + r * PA + c0 + u) = h;
                }
            }
        }
        __syncthreads();

#pragma unroll
        for (int ks = 0; ks < 4; ++ks) {
            const int kb = ks * 8;
            uint32_t aH[2][4], aL[2][4];
#pragma unroll
            for (int mt = 0; mt < 2; ++mt) {
                const float* ap = aHi + (wm + mt * 16 + g) * PA + kb + t;
                aH[mt][0] = __float_as_uint(ap[0]);
                aH[mt][1] = __float_as_uint(ap[8 * PA]);
                aH[mt][2] = __float_as_uint(ap[4]);
                aH[mt][3] = __float_as_uint(ap[8 * PA + 4]);
                if constexpr (SPLIT == 3) {
                    const float* al = aLo + (wm + mt * 16 + g) * PA + kb + t;
                    aL[mt][0] = __float_as_uint(al[0]);
                    aL[mt][1] = __float_as_uint(al[8 * PA]);
                    aL[mt][2] = __float_as_uint(al[4]);
                    aL[mt][3] = __float_as_uint(al[8 * PA + 4]);
                }
            }
#pragma unroll
            for (int nt = 0; nt < NT; ++nt) {
                const float* bp = bHi + (wn + nt * 8 + g) * PA + kb + t;
                const uint32_t bH0 = __float_as_uint(bp[0]);
                const uint32_t bH1 = __float_as_uint(bp[4]);
#pragma unroll
                for (int mt = 0; mt < 2; ++mt) mma8(acc[mt][nt], aH[mt], bH0, bH1);
                if constexpr (SPLIT == 3) {
                    const float* bl = bLo + (wn + nt * 8 + g) * PA + kb + t;
                    const uint32_t bL0 = __float_as_uint(bl[0]);
                    const uint32_t bL1 = __float_as_uint(bl[4]);
#pragma unroll
                    for (int mt = 0; mt < 2; ++mt) {
                        mma8(acc[mt][nt], aH[mt], bL0, bL1);
                        mma8(acc[mt][nt], aL[mt], bH0, bH1);
                    }
                }
            }
        }
    }

    __syncthreads();
#pragma unroll
    for (int mt = 0; mt < 2; ++mt)
#pragma unroll
        for (int nt = 0; nt < NT; ++nt) {
            const int row = wm + mt * 16 + g;
            const int col = wn + nt * 8 + t * 2;
            *(float2*)&sf[row * PEPI + col]       = make_float2(acc[mt][nt][0], acc[mt][nt][1]);
            *(float2*)&sf[(row + 8) * PEPI + col] = make_float2(acc[mt][nt][2], acc[mt][nt][3]);
        }
    __syncthreads();
#pragma unroll
    for (int i = tid; i < 128 * (BN / 4); i += 256) {
        const int row = i / (BN / 4), c4 = (i % (BN / 4)) * 4;
        *(float4*)(Cbase + (size_t)row * ldc + c4) = *(const float4*)&sf[row * PEPI + c4];
    }
}

// ---------------------------------------------------------------------------
// Flash attention: fused QK^T (3xTF32) + online softmax + PV (tf32).
// One CTA = 128 queries of one (b,h); 8 warps x 16 rows; tiles of 64 keys.
// ---------------------------------------------------------------------------
#define FPQ 68             /* pitch (mod 32 = 4 -> conflict-free fragments) */
#define FLASH_SMEM ((128*2 + 64*2 + 64 + 128) * FPQ * 4)   /* 156672 B */

__global__ void __launch_bounds__(256, 1) flash_kernel()
{
    extern __shared__ float sf[];
    float* Qh = sf;                    // [row][d]   128 x 64
    float* Ql = Qh + 128 * FPQ;
    float* Kh = Ql + 128 * FPQ;        // [tok][d]    64 x 64
    float* Kl = Kh + 64 * FPQ;
    float* Vt = Kl + 64 * FPQ;         // [d][tok]    64 x 64
    float* Ps = Vt + 64 * FPQ;         // [row][tok] 128 x 64 (warp-private rows)

    const int tid = threadIdx.x, wid = tid >> 5, lane = tid & 31;
    const int g = lane >> 2, t = lane & 3;
    const int wm = wid * 16;
    const int bm = blockIdx.x * 128;
    const int bh = blockIdx.y, b = bh >> 4, h = bh & (HEADS - 1);

    const float* qbase = g_qkv + (size_t)b * SEQ * QKVW + h * KDIM;
    const float* kbase = qbase + EMBED;
    const float* vbase = qbase + 2 * EMBED;

    // Q tile: prescale by 1/8 (exact), 3x-split into smem
    {
        const int r = tid >> 1, c0 = (tid & 1) * 32;
        const float* p = qbase + (size_t)(bm + r) * QKVW + c0;
#pragma unroll
        for (int u = 0; u < 32; u += 4) {
            float4 v = *(const float4*)(p + u);
            v.x *= 0.125f; v.y *= 0.125f; v.z *= 0.125f; v.w *= 0.125f;
            float4 hh, ll;
            hh.x = tf32r(v.x); ll.x = tf32r(v.x - hh.x);
            hh.y = tf32r(v.y); ll.y = tf32r(v.y - hh.y);
            hh.z = tf32r(v.z); ll.z = tf32r(v.z - hh.z);
            hh.w = tf32r(v.w); ll.w = tf32r(v.w - hh.w);
            *(float4*)(Qh + r * FPQ + c0 + u) = hh;
            *(float4*)(Ql + r * FPQ + c0 + u) = ll;
        }
    }
    __syncthreads();

    // Hoist Q fragments to registers for the whole kernel
    uint32_t qh[8][4], ql[8][4];
#pragma unroll
    for (int ks = 0; ks < 8; ++ks) {
        const float* ap = Qh + (wm + g) * FPQ + ks * 8 + t;
        const float* al = Ql + (wm + g) * FPQ + ks * 8 + t;
        qh[ks][0] = __float_as_uint(ap[0]);
        qh[ks][1] = __float_as_uint(ap[8 * FPQ]);
        qh[ks][2] = __float_as_uint(ap[4]);
        qh[ks][3] = __float_as_uint(ap[8 * FPQ + 4]);
        ql[ks][0] = __float_as_uint(al[0]);
        ql[ks][1] = __float_as_uint(al[8 * FPQ]);
        ql[ks][2] = __float_as_uint(al[4]);
        ql[ks][3] = __float_as_uint(al[8 * FPQ + 4]);
    }

    float m0 = -1e30f, m1 = -1e30f, l0 = 0.f, l1 = 0.f;
    float o[8][4];
#pragma unroll
    for (int nt = 0; nt < 8; nt++)
#pragma unroll
        for (int i = 0; i < 4; i++) o[nt][i] = 0.f;

    for (int kt = 0; kt < SEQ; kt += 64) {
        __syncthreads();    // previous tile's PV reads done before K/V overwrite
        // K tile [64 tok x 64 d], 3x-split
        {
            const int r = tid >> 2, c0 = (tid & 3) * 16;
            const float* p = kbase + (size_t)(kt + r) * QKVW + c0;
#pragma unroll
            for (int u = 0; u < 16; u += 4) {
                float4 v = *(const float4*)(p + u);
                float4 hh, ll;
                hh.x = tf32r(v.x); ll.x = tf32r(v.x - hh.x);
                hh.y = tf32r(v.y); ll.y = tf32r(v.y - hh.y);
                hh.z = tf32r(v.z); ll.z = tf32r(v.z - hh.z);
                hh.w = tf32r(v.w); ll.w = tf32r(v.w - hh.w);
                *(float4*)(Kh + r * FPQ + c0 + u) = hh;
                *(float4*)(Kl + r * FPQ + c0 + u) = ll;
            }
        }
        // V tile transposed -> Vt[d][tok] (tf32 rounded)
#pragma unroll
        for (int it = 0; it < 4; ++it) {
            const int task = tid + it * 256;
            const int tok = task >> 4, q4 = (task & 15) * 4;
            float4 v = *(const float4*)(vbase + (size_t)(kt + tok) * QKVW + q4);
            Vt[(q4 + 0) * FPQ + tok] = tf32r(v.x);
            Vt[(q4 + 1) * FPQ + tok] = tf32r(v.y);
            Vt[(q4 + 2) * FPQ + tok] = tf32r(v.z);
            Vt[(q4 + 3) * FPQ + tok] = tf32r(v.w);
        }
        __syncthreads();

        // S = Q K^T (3xTF32)
        float s[8][4];
#pragma unroll
        for (int nt = 0; nt < 8; nt++)
#pragma unroll
            for (int i = 0; i < 4; i++) s[nt][i] = 0.f;
#pragma unroll
        for (int ks = 0; ks < 8; ++ks) {
#pragma unroll
            for (int nt = 0; nt < 8; ++nt) {
                const float* bp = Kh + (nt * 8 + g) * FPQ + ks * 8 + t;
                const float* bl = Kl + (nt * 8 + g) * FPQ + ks * 8 + t;
                const uint32_t bH0 = __float_as_uint(bp[0]);
                const uint32_t bH1 = __float_as_uint(bp[4]);
                const uint32_t bL0 = __float_as_uint(bl[0]);
                const uint32_t bL1 = __float_as_uint(bl[4]);
                mma8(s[nt], qh[ks], bH0, bH1);
                mma8(s[nt], qh[ks], bL0, bL1);
                mma8(s[nt], ql[ks], bH0, bH1);
            }
        }

        // Online softmax (rows wm+g and wm+g+8; stats shared within quad)
        float mx0 = -1e30f, mx1 = -1e30f;
#pragma unroll
        for (int nt = 0; nt < 8; nt++) {
            mx0 = fmaxf(mx0, fmaxf(s[nt][0], s[nt][1]));
            mx1 = fmaxf(mx1, fmaxf(s[nt][2], s[nt][3]));
        }
        mx0 = fmaxf(mx0, __shfl_xor_sync(~0u, mx0, 1));
        mx0 = fmaxf(mx0, __shfl_xor_sync(~0u, mx0, 2));
        mx1 = fmaxf(mx1, __shfl_xor_sync(~0u, mx1, 1));
        mx1 = fmaxf(mx1, __shfl_xor_sync(~0u, mx1, 2));
        const float mn0 = fmaxf(m0, mx0), mn1 = fmaxf(m1, mx1);
        const float cr0 = __expf(m0 - mn0), cr1 = __expf(m1 - mn1);
        m0 = mn0; m1 = mn1;
        float ls0 = 0.f, ls1 = 0.f;
#pragma unroll
        for (int nt = 0; nt < 8; nt++) {
            s[nt][0] = __expf(s[nt][0] - mn0);
            s[nt][1] = __expf(s[nt][1] - mn0);
            s[nt][2] = __expf(s[nt][2] - mn1);
            s[nt][3] = __expf(s[nt][3] - mn1);
            ls0 += s[nt][0] + s[nt][1];
            ls1 += s[nt][2] + s[nt][3];
        }
        ls0 += __shfl_xor_sync(~0u, ls0, 1);
        ls0 += __shfl_xor_sync(~0u, ls0, 2);
        ls1 += __shfl_xor_sync(~0u, ls1, 1);
        ls1 += __shfl_xor_sync(~0u, ls1, 2);
        l0 = l0 * cr0 + ls0;
        l1 = l1 * cr1 + ls1;
#pragma unroll
        for (int nt = 0; nt < 8; nt++) {
            o[nt][0] *= cr0; o[nt][1] *= cr0;
            o[nt][2] *= cr1; o[nt][3] *= cr1;
        }

        // Stage P (C-frag layout -> A-frag layout), warp-private rows
#pragma unroll
        for (int nt = 0; nt < 8; nt++) {
            *(float2*)&Ps[(wm + g) * FPQ + nt * 8 + 2 * t] =
                make_float2(tf32r(s[nt][0]), tf32r(s[nt][1]));
            *(float2*)&Ps[(wm + g + 8) * FPQ + nt * 8 + 2 * t] =
                make_float2(tf32r(s[nt][2]), tf32r(s[nt][3]));
        }
        __syncwarp();

        // O += P V (1xTF32)
#pragma unroll
        for (int ks = 0; ks < 8; ++ks) {
            uint32_t a[4];
            const float* ap = Ps + (wm + g) * FPQ + ks * 8 + t;
            a[0] = __float_as_uint(ap[0]);
            a[1] = __float_as_uint(ap[8 * FPQ]);
            a[2] = __float_as_uint(ap[4]);
            a[3] = __float_as_uint(ap[8 * FPQ + 4]);
#pragma unroll
            for (int nt = 0; nt < 8; ++nt) {
                const float* bp = Vt + (nt * 8 + g) * FPQ + ks * 8 + t;
                mma8(o[nt], a, __float_as_uint(bp[0]), __float_as_uint(bp[4]));
            }
        }
    }

    // Epilogue: normalize and write heads
    const float i0 = 1.f / l0, i1 = 1.f / l1;
    float* dst0 = g_heads + (size_t)(b * SEQ + bm + wm + g) * EMBED + h * KDIM;
    float* dst1 = dst0 + 8 * EMBED;
#pragma unroll
    for (int nt = 0; nt < 8; nt++) {
        *(float2*)(dst0 + nt * 8 + 2 * t) = make_float2(o[nt][0] * i0, o[nt][1] * i0);
        *(float2*)(dst1 + nt * 8 + 2 * t) = make_float2(o[nt][2] * i1, o[nt][3] * i1);
    }
}

// ---------------------------------------------------------------------------
#define SMF(stage, epi) (((stage) > (epi) ? (stage) : (epi)) * 4)
#define SM_QKV3 SMF((128 * PA) * 2 + (128 * PA) * 2, 128 * 132)   /* 73728 */
#define SM_QKV1 SMF((128 * PA) + (128 * PA), 128 * 132)           /* 67584 */
#define SM_OP   SM_QKV1

extern "C" void kernel_launch(void* const* d_in, const int* in_sizes, int n_in,
                              void* d_out, int out_size)
{
    const float* x  = (const float*)d_in[0];
    const float* wq = (const float*)d_in[1];
    const float* wk = (const float*)d_in[2];
    const float* wv = (const float*)d_in[3];
    const float* w  = (const float*)d_in[4];
    float* out = (float*)d_out;

    cudaFuncSetAttribute(gemm_kernel<MODE_QKV,   128, 3, 1024>,
                         cudaFuncAttributeMaxDynamicSharedMemorySize, SM_QKV3);
    cudaFuncSetAttribute(gemm_kernel<MODE_QKV,   128, 1, 1024>,
                         cudaFuncAttributeMaxDynamicSharedMemorySize, SM_QKV1);
    cudaFuncSetAttribute(gemm_kernel<MODE_OPROJ, 128, 1, 1024>,
                         cudaFuncAttributeMaxDynamicSharedMemorySize, SM_OP);
    cudaFuncSetAttribute(flash_kernel,
                         cudaFuncAttributeMaxDynamicSharedMemorySize, FLASH_SMEM);

    // 0. transpose weights once
    prep_kernel<<<(QKVW * 256 + EMBED * 256) / 256, 256>>>(wq, wk, wv, w);

    // 1a. Q,K projection (3xTF32): columns [0, 2048)
    gemm_kernel<MODE_QKV, 128, 3, 1024>
        <<<dim3(16, TOKENS / 128), 256, SM_QKV3>>>(x, out, 0);

    // 1b. V projection (1xTF32): columns [2048, 3072)
    gemm_kernel<MODE_QKV, 128, 1, 1024>
        <<<dim3(8, TOKENS / 128), 256, SM_QKV1>>>(x, out, 16);

    // 2. fused attention: g_heads = softmax(Q K^T / 8) V
    flash_kernel<<<dim3(SEQ / 128, BH), 256, FLASH_SMEM>>>();

    // 3. output projection (tf32): out = heads @ w
    gemm_kernel<MODE_OPROJ, 128, 1, 1024>
        <<<dim3(EMBED / 128, TOKENS / 128), 256, SM_OP>>>(x, out, 0);
}